// round 9
// baseline (speedup 1.0000x reference)
#include <cuda_runtime.h>
#include <cuda_bf16.h>

// Fused single-kernel deterministic reduction: out = sum(x) * a * b
// x: 8192*8192 fp32 (d_in[0]), a,b: scalar fp32 (d_in[1], d_in[2]).
//
// Mainloop shape identical to the R7 winner (4 independent LDG.128 off one
// base register with +0/+4KB/+8KB/+12KB immediate offsets -> guaranteed
// 4-deep memory pipeline at 29 regs). Grid doubled to 2048 CTAs of 128KB
// contiguous chunks: halves the straggler-CTA tail quantum that capped
// occupancy at 82% with 1024 CTAs. 2048 * 8192 = 2^24 float4 exactly:
// uniform trip count, zero bounds checks.

#define R_BLOCKS  2048
#define R_THREADS 256
#define R_CHUNK   8192   // float4 per block
#define R_GROUPS  8      // 8 groups * 4 loads = 32 float4 per thread

__device__ float g_partials[R_BLOCKS];
__device__ unsigned int g_count = 0;   // self-resetting: graph-replay safe

__device__ __forceinline__ float block_reduce(float s)
{
    #pragma unroll
    for (int o = 16; o > 0; o >>= 1)
        s += __shfl_xor_sync(0xffffffffu, s, o);

    __shared__ float sh[R_THREADS / 32];
    int lane = threadIdx.x & 31;
    int warp = threadIdx.x >> 5;
    if (lane == 0) sh[warp] = s;
    __syncthreads();

    if (warp == 0) {
        s = (lane < (R_THREADS / 32)) ? sh[lane] : 0.f;
        #pragma unroll
        for (int o = 16; o > 0; o >>= 1)
            s += __shfl_xor_sync(0xffffffffu, s, o);
    }
    return s;  // valid in warp 0 lane 0
}

__global__ void __launch_bounds__(R_THREADS) reduce_fused(
    const float4* __restrict__ x4,
    const float* __restrict__ a, const float* __restrict__ b,
    float* __restrict__ out)
{
    const float4* p = x4 + (unsigned)blockIdx.x * (unsigned)R_CHUNK + threadIdx.x;

    float s0 = 0.f, s1 = 0.f, s2 = 0.f, s3 = 0.f;

    #pragma unroll 1
    for (int g = 0; g < R_GROUPS; g++) {
        // 4 independent LDG.128 off one base register (+0/+4KB/+8KB/+12KB),
        // all issued before any consumer -> 4-deep memory pipeline.
        float4 v0 = p[0];
        float4 v1 = p[256];
        float4 v2 = p[512];
        float4 v3 = p[768];
        s0 += (v0.x + v1.x) + (v2.x + v3.x);
        s1 += (v0.y + v1.y) + (v2.y + v3.y);
        s2 += (v0.z + v1.z) + (v2.z + v3.z);
        s3 += (v0.w + v1.w) + (v2.w + v3.w);
        p += 1024;
    }

    float s = block_reduce((s0 + s1) + (s2 + s3));

    __shared__ bool is_last;
    if (threadIdx.x == 0) {
        g_partials[blockIdx.x] = s;
        __threadfence();
        unsigned int prev = atomicAdd(&g_count, 1u);
        is_last = (prev == (unsigned)(R_BLOCKS - 1));
    }
    __syncthreads();

    if (is_last) {
        // Deterministic final fold: fixed per-thread strided order.
        float t = 0.f;
        #pragma unroll
        for (int i = 0; i < R_BLOCKS / R_THREADS; i++)
            t += g_partials[threadIdx.x + i * R_THREADS];
        t = block_reduce(t);
        if (threadIdx.x == 0) {
            out[0] = t * a[0] * b[0];
            g_count = 0;   // reset for next graph replay
        }
    }
}

extern "C" void kernel_launch(void* const* d_in, const int* in_sizes, int n_in,
                              void* d_out, int out_size)
{
    const float4* x4 = (const float4*)d_in[0];
    const float* a   = (const float*)d_in[1];
    const float* b   = (const float*)d_in[2];
    float* out       = (float*)d_out;

    reduce_fused<<<R_BLOCKS, R_THREADS>>>(x4, a, b, out);
}